// round 9
// baseline (speedup 1.0000x reference)
#include <cuda_runtime.h>
#include <math.h>
#include <stdint.h>

#define BATCH 4
#define SEQ   4096
#define EMB   1024
#define HD    128
#define MTOT  (BATCH * SEQ)

// Scratch for projected q, k, v (fp32), allocation-free device globals
__device__ float g_q[(size_t)MTOT * HD];
__device__ float g_k[(size_t)MTOT * HD];
__device__ float g_v[(size_t)MTOT * HD];

// ---------------------------------------------------------------------------
// tf32 helpers
// ---------------------------------------------------------------------------
__device__ __forceinline__ uint32_t f2tf(float f) {
    uint32_t u;
    asm("cvt.rna.tf32.f32 %0, %1;" : "=r"(u) : "f"(f));
    return u;
}

// D += A(16x8, tf32, row) * B(8x8, tf32, col); accumulate in place.
__device__ __forceinline__ void mma8(float* d, const uint32_t* a, const uint32_t* b) {
    asm volatile(
        "mma.sync.aligned.m16n8k8.row.col.f32.tf32.tf32.f32 "
        "{%0,%1,%2,%3}, {%4,%5,%6,%7}, {%8,%9}, {%0,%1,%2,%3};\n"
        : "+f"(d[0]), "+f"(d[1]), "+f"(d[2]), "+f"(d[3])
        : "r"(a[0]), "r"(a[1]), "r"(a[2]), "r"(a[3]), "r"(b[0]), "r"(b[1]));
}

// ---------------------------------------------------------------------------
// Kernel 1: QKV projection, out[which] = x[M,E] @ W[E,H], tf32 MMA.
// CTA tile 128(M) x 128(N=HD), BK=32. 8 warps: warp tile 32x64.
// ---------------------------------------------------------------------------
#define XSTR 36     // 36 % 32 == 4  -> A-frag loads conflict-free
#define WSTR 136    // 136 % 32 == 8 -> B-frag loads conflict-free

__global__ __launch_bounds__(256) void qkv_kernel(
    const float* __restrict__ x,
    const float* __restrict__ Wq,
    const float* __restrict__ Wk,
    const float* __restrict__ Wv)
{
    const int which = blockIdx.y;
    const float* __restrict__ W = (which == 0) ? Wq : (which == 1) ? Wk : Wv;
    float* __restrict__ out = (which == 0) ? g_q : (which == 1) ? g_k : g_v;

    __shared__ uint32_t Xs[128 * XSTR];
    __shared__ uint32_t Ws[32 * WSTR];

    const int tid  = threadIdx.x;
    const int warp = tid >> 5;
    const int lane = tid & 31;
    const int g = lane >> 2;
    const int t = lane & 3;
    const int wm = warp & 3;        // 4 M bands of 32
    const int wn = warp >> 2;       // 2 N halves of 64
    const int m0 = wm * 32;
    const int n0 = wn * 64;
    const int row_base = blockIdx.x * 128;

    float acc[2][8][4];
#pragma unroll
    for (int i = 0; i < 2; i++)
#pragma unroll
        for (int j = 0; j < 8; j++)
#pragma unroll
            for (int r = 0; r < 4; r++) acc[i][j][r] = 0.f;

    for (int k0 = 0; k0 < EMB; k0 += 32) {
        // stage X tile 128x32 (1024 float4, 4/thread)
#pragma unroll
        for (int it = 0; it < 4; it++) {
            int idx = tid + it * 256;
            int r = idx >> 3;
            int c = (idx & 7) * 4;
            float4 v = *(const float4*)&x[(size_t)(row_base + r) * EMB + k0 + c];
            uint4 u = make_uint4(f2tf(v.x), f2tf(v.y), f2tf(v.z), f2tf(v.w));
            *(uint4*)&Xs[r * XSTR + c] = u;
        }
        // stage W tile 32x128 (1024 float4, 4/thread)
#pragma unroll
        for (int it = 0; it < 4; it++) {
            int idx = tid + it * 256;
            int r = idx >> 5;
            int c = (idx & 31) * 4;
            float4 v = *(const float4*)&W[(size_t)(k0 + r) * HD + c];
            uint4 u = make_uint4(f2tf(v.x), f2tf(v.y), f2tf(v.z), f2tf(v.w));
            *(uint4*)&Ws[r * WSTR + c] = u;
        }
        __syncthreads();

#pragma unroll
        for (int ks = 0; ks < 4; ks++) {
            const int kk = ks * 8;
            uint32_t a[2][4];
#pragma unroll
            for (int i = 0; i < 2; i++) {
                int ab = (m0 + i * 16 + g) * XSTR + kk + t;
                a[i][0] = Xs[ab];
                a[i][1] = Xs[ab + 8 * XSTR];
                a[i][2] = Xs[ab + 4];
                a[i][3] = Xs[ab + 8 * XSTR + 4];
            }
#pragma unroll
            for (int j = 0; j < 8; j++) {
                int bb = (kk + t) * WSTR + n0 + j * 8 + g;
                uint32_t b[2] = { Ws[bb], Ws[bb + 4 * WSTR] };
                mma8(acc[0][j], a[0], b);
                mma8(acc[1][j], a[1], b);
            }
        }
        __syncthreads();
    }

#pragma unroll
    for (int i = 0; i < 2; i++)
#pragma unroll
        for (int j = 0; j < 8; j++) {
            int row = row_base + m0 + i * 16 + g;
            int col = n0 + j * 8 + 2 * t;
            *(float2*)&out[(size_t)row * HD + col] =
                make_float2(acc[i][j][0], acc[i][j][1]);
            *(float2*)&out[(size_t)(row + 8) * HD + col] =
                make_float2(acc[i][j][2], acc[i][j][3]);
        }
}

// ---------------------------------------------------------------------------
// Kernel 2: causal flash attention, tf32 MMA.
// BM=64 queries, BN=64 keys per iter. 8 warps: warp w owns m16 tile (w&3),
// n-half (w>>2). Softmax stats in registers + small smem exchange per iter.
// ---------------------------------------------------------------------------
#define QKSTR 132   // 132 % 32 == 4 (A-pattern rows: Q, K)
#define VSTR  136   // 136 % 32 == 8 (B-pattern rows: V)
#define PSTR  68    // 68  % 32 == 4 (A-pattern rows: P)

#define ATTN_SMEM_U32 (2 * 64 * QKSTR + 64 * VSTR + 64 * PSTR + 4 * 64)
#define ATTN_SMEM_BYTES (ATTN_SMEM_U32 * 4)

__global__ __launch_bounds__(256) void attn_kernel(float* __restrict__ out)
{
    const int batch = blockIdx.y;
    const int qt = (int)(gridDim.x - 1) - (int)blockIdx.x;   // heavy tiles first
    const int q_base = qt * 64;
    const size_t boff = (size_t)batch * SEQ * HD;

    extern __shared__ uint32_t sm[];
    uint32_t* Qs = sm;                      // 64 x 132
    uint32_t* Ks = Qs + 64 * QKSTR;         // 64 x 132
    uint32_t* Vs = Ks + 64 * QKSTR;         // 64 x 136
    uint32_t* Ps = Vs + 64 * VSTR;          // 64 x 68
    float* redmax = (float*)(Ps + 64 * PSTR);   // [2][64]
    float* redsum = redmax + 2 * 64;            // [2][64]

    const int tid  = threadIdx.x;
    const int warp = tid >> 5;
    const int lane = tid & 31;
    const int g = lane >> 2;
    const int t = lane & 3;
    const int mt = warp & 3;        // m16 tile index
    const int nh = warp >> 2;       // n / hd half
    const int m0 = mt * 16;
    const int nb = nh * 32;         // key-col base for S
    const int hb = nh * 64;         // hd-col base for O
    const int r0l = m0 + g;         // local rows this thread owns
    const int r1l = m0 + g + 8;

    const float qscale = rsqrtf((float)HD);

    // stage Q (scaled, tf32): 64x128 = 2048 float4, 8 per thread
#pragma unroll
    for (int it = 0; it < 8; it++) {
        int idx = tid + it * 256;
        int r = idx >> 5;
        int c = (idx & 31) * 4;
        float4 v = *(const float4*)&g_q[boff + (size_t)(q_base + r) * HD + c];
        uint4 u = make_uint4(f2tf(v.x * qscale), f2tf(v.y * qscale),
                             f2tf(v.z * qscale), f2tf(v.w * qscale));
        *(uint4*)&Qs[r * QKSTR + c] = u;
    }

    float o[8][4];
#pragma unroll
    for (int j = 0; j < 8; j++)
#pragma unroll
        for (int r = 0; r < 4; r++) o[j][r] = 0.f;

    float m_i0 = -1e30f, m_i1 = -1e30f;
    float l_i0 = 0.f,    l_i1 = 0.f;

    for (int kt = 0; kt <= qt; kt++) {
        __syncthreads();    // prior iter's PV reads / Q staging visible

        // stage K, V tiles (tf32): 2 x 2048 float4, 16 per thread
        const int k_base = kt * 64;
#pragma unroll
        for (int it = 0; it < 8; it++) {
            int idx = tid + it * 256;
            int r = idx >> 5;
            int c = (idx & 31) * 4;
            float4 kv = *(const float4*)&g_k[boff + (size_t)(k_base + r) * HD + c];
            *(uint4*)&Ks[r * QKSTR + c] =
                make_uint4(f2tf(kv.x), f2tf(kv.y), f2tf(kv.z), f2tf(kv.w));
            float4 vv = *(const float4*)&g_v[boff + (size_t)(k_base + r) * HD + c];
            *(uint4*)&Vs[r * VSTR + c] =
                make_uint4(f2tf(vv.x), f2tf(vv.y), f2tf(vv.z), f2tf(vv.w));
        }
        __syncthreads();

        // S = Q @ K^T  (warp: 1 m-tile x 4 n-tiles, k=128)
        float s[4][4];
#pragma unroll
        for (int j = 0; j < 4; j++)
#pragma unroll
            for (int r = 0; r < 4; r++) s[j][r] = 0.f;

#pragma unroll
        for (int ks = 0; ks < 16; ks++) {
            const int kk = ks * 8;
            uint32_t a[4];
            int ab = r0l * QKSTR + kk + t;
            a[0] = Qs[ab];
            a[1] = Qs[ab + 8 * QKSTR];
            a[2] = Qs[ab + 4];
            a[3] = Qs[ab + 8 * QKSTR + 4];
#pragma unroll
            for (int j = 0; j < 4; j++) {
                int bb = (nb + j * 8 + g) * QKSTR + kk + t;
                uint32_t b[2] = { Ks[bb], Ks[bb + 4] };
                mma8(s[j], a, b);
            }
        }

        // causal mask on diagonal tile
        if (kt == qt) {
#pragma unroll
            for (int j = 0; j < 4; j++) {
                int cn = nb + j * 8 + 2 * t;
                if (cn     > r0l) s[j][0] = -1e30f;
                if (cn + 1 > r0l) s[j][1] = -1e30f;
                if (cn     > r1l) s[j][2] = -1e30f;
                if (cn + 1 > r1l) s[j][3] = -1e30f;
            }
        }

        // per-half row max -> smem
        float mx0 = -1e30f, mx1 = -1e30f;
#pragma unroll
        for (int j = 0; j < 4; j++) {
            mx0 = fmaxf(mx0, fmaxf(s[j][0], s[j][1]));
            mx1 = fmaxf(mx1, fmaxf(s[j][2], s[j][3]));
        }
        mx0 = fmaxf(mx0, __shfl_xor_sync(0xffffffffu, mx0, 1));
        mx0 = fmaxf(mx0, __shfl_xor_sync(0xffffffffu, mx0, 2));
        mx1 = fmaxf(mx1, __shfl_xor_sync(0xffffffffu, mx1, 1));
        mx1 = fmaxf(mx1, __shfl_xor_sync(0xffffffffu, mx1, 2));
        if (t == 0) {
            redmax[nh * 64 + r0l] = mx0;
            redmax[nh * 64 + r1l] = mx1;
        }
        __syncthreads();

        const float m_new0 = fmaxf(m_i0, fmaxf(redmax[r0l], redmax[64 + r0l]));
        const float m_new1 = fmaxf(m_i1, fmaxf(redmax[r1l], redmax[64 + r1l]));

        // exp, P -> smem (tf32), per-half row sum -> smem
        float sum0 = 0.f, sum1 = 0.f;
#pragma unroll
        for (int j = 0; j < 4; j++) {
            float p00 = __expf(s[j][0] - m_new0);
            float p01 = __expf(s[j][1] - m_new0);
            float p10 = __expf(s[j][2] - m_new1);
            float p11 = __expf(s[j][3] - m_new1);
            sum0 += p00 + p01;
            sum1 += p10 + p11;
            int cn = nb + j * 8 + 2 * t;
            *(uint2*)&Ps[r0l * PSTR + cn] = make_uint2(f2tf(p00), f2tf(p01));
            *(uint2*)&Ps[r1l * PSTR + cn] = make_uint2(f2tf(p10), f2tf(p11));
        }
        sum0 += __shfl_xor_sync(0xffffffffu, sum0, 1);
        sum0 += __shfl_xor_sync(0xffffffffu, sum0, 2);
        sum1 += __shfl_xor_sync(0xffffffffu, sum1, 1);
        sum1 += __shfl_xor_sync(0xffffffffu, sum1, 2);
        if (t == 0) {
            redsum[nh * 64 + r0l] = sum0;
            redsum[nh * 64 + r1l] = sum1;
        }
        __syncthreads();

        const float corr0 = __expf(m_i0 - m_new0);
        const float corr1 = __expf(m_i1 - m_new1);
        l_i0 = l_i0 * corr0 + redsum[r0l] + redsum[64 + r0l];
        l_i1 = l_i1 * corr1 + redsum[r1l] + redsum[64 + r1l];
        m_i0 = m_new0;
        m_i1 = m_new1;

        // rescale O, then O += P @ V
#pragma unroll
        for (int j = 0; j < 8; j++) {
            o[j][0] *= corr0; o[j][1] *= corr0;
            o[j][2] *= corr1; o[j][3] *= corr1;
        }
#pragma unroll
        for (int ks = 0; ks < 8; ks++) {
            const int kk = ks * 8;
            uint32_t a[4];
            int ab = r0l * PSTR + kk + t;
            a[0] = Ps[ab];
            a[1] = Ps[ab + 8 * PSTR];
            a[2] = Ps[ab + 4];
            a[3] = Ps[ab + 8 * PSTR + 4];
#pragma unroll
            for (int j = 0; j < 8; j++) {
                int bb = (kk + t) * VSTR + hb + j * 8 + g;
                uint32_t b[2] = { Vs[bb], Vs[bb + 4 * VSTR] };
                mma8(o[j], a, b);
            }
        }
    }

    // normalize and write
    const float inv0 = 1.f / l_i0;
    const float inv1 = 1.f / l_i1;
#pragma unroll
    for (int j = 0; j < 8; j++) {
        int col = hb + j * 8 + 2 * t;
        int row = q_base + r0l;
        *(float2*)&out[boff + (size_t)row * HD + col] =
            make_float2(o[j][0] * inv0, o[j][1] * inv0);
        *(float2*)&out[boff + (size_t)(row + 8) * HD + col] =
            make_float2(o[j][2] * inv1, o[j][3] * inv1);
    }
}

// ---------------------------------------------------------------------------
extern "C" void kernel_launch(void* const* d_in, const int* in_sizes, int n_in,
                              void* d_out, int out_size)
{
    const float* x  = (const float*)d_in[0];
    const float* Wq = (const float*)d_in[1];
    const float* Wk = (const float*)d_in[2];
    const float* Wv = (const float*)d_in[3];
    float* out = (float*)d_out;

    cudaFuncSetAttribute(attn_kernel,
                         cudaFuncAttributeMaxDynamicSharedMemorySize,
                         ATTN_SMEM_BYTES);

    qkv_kernel<<<dim3(MTOT / 128, 3), 256>>>(x, Wq, Wk, Wv);
    attn_kernel<<<dim3(SEQ / 64, BATCH), 256, ATTN_SMEM_BYTES>>>(out);
}

// round 11
// speedup vs baseline: 1.2309x; 1.2309x over previous
#include <cuda_runtime.h>
#include <math.h>
#include <stdint.h>

#define BATCH 4
#define SEQ   4096
#define EMB   1024
#define HD    128
#define MTOT  (BATCH * SEQ)

// Projected q (pre-scaled), k, v stored as tf32 bit patterns (fp32 container).
__device__ float g_q[(size_t)MTOT * HD];
__device__ float g_k[(size_t)MTOT * HD];
__device__ float g_v[(size_t)MTOT * HD];

// ---------------------------------------------------------------------------
// helpers
// ---------------------------------------------------------------------------
__device__ __forceinline__ uint32_t f2tf(float f) {
    uint32_t u;
    asm("cvt.rna.tf32.f32 %0, %1;" : "=r"(u) : "f"(f));
    return u;
}

__device__ __forceinline__ void mma8(float* d, const uint32_t* a, const uint32_t* b) {
    asm volatile(
        "mma.sync.aligned.m16n8k8.row.col.f32.tf32.tf32.f32 "
        "{%0,%1,%2,%3}, {%4,%5,%6,%7}, {%8,%9}, {%0,%1,%2,%3};\n"
        : "+f"(d[0]), "+f"(d[1]), "+f"(d[2]), "+f"(d[3])
        : "r"(a[0]), "r"(a[1]), "r"(a[2]), "r"(a[3]), "r"(b[0]), "r"(b[1]));
}

__device__ __forceinline__ uint32_t smem_u32(const void* p) {
    uint32_t a;
    asm("{ .reg .u64 t; cvta.to.shared.u64 t, %1; cvt.u32.u64 %0, t; }"
        : "=r"(a) : "l"(p));
    return a;
}

__device__ __forceinline__ void cp16(uint32_t dst, const void* src) {
    asm volatile("cp.async.cg.shared.global [%0], [%1], 16;" :: "r"(dst), "l"(src));
}
#define CP_COMMIT() asm volatile("cp.async.commit_group;")
#define CP_WAIT0()  asm volatile("cp.async.wait_group 0;" ::: "memory")

// ---------------------------------------------------------------------------
// Kernel 1: QKV projection, tf32 MMA, cp.async double-buffered staging.
// CTA tile 128(M) x 128(N), BK=32, 8 warps (32x64 warp tile).
// Epilogue converts outputs to tf32 (Q also pre-scaled by 1/sqrt(HD)).
// ---------------------------------------------------------------------------
#define XSTR 36     // % 32 == 4 (A pattern)
#define WSTR 136    // % 32 == 8 (B pattern)
#define XBUF (128 * XSTR)
#define WBUF (32 * WSTR)
#define QKV_SMEM_BYTES ((2 * XBUF + 2 * WBUF) * 4)

__global__ __launch_bounds__(256) void qkv_kernel(
    const float* __restrict__ x,
    const float* __restrict__ Wq,
    const float* __restrict__ Wk,
    const float* __restrict__ Wv)
{
    const int which = blockIdx.y;
    const float* __restrict__ W = (which == 0) ? Wq : (which == 1) ? Wk : Wv;
    float* __restrict__ out = (which == 0) ? g_q : (which == 1) ? g_k : g_v;

    extern __shared__ uint32_t qsm[];
    uint32_t* Xs = qsm;                 // [2][128*36] raw fp32 bits
    uint32_t* Ws = qsm + 2 * XBUF;      // [2][32*136]
    const uint32_t xs_a = smem_u32(Xs);
    const uint32_t ws_a = smem_u32(Ws);

    const int tid  = threadIdx.x;
    const int warp = tid >> 5;
    const int lane = tid & 31;
    const int g = lane >> 2;
    const int t = lane & 3;
    const int m0 = (warp & 3) * 32;
    const int n0 = (warp >> 2) * 64;
    const int row_base = blockIdx.x * 128;

    float acc[2][8][4];
#pragma unroll
    for (int i = 0; i < 2; i++)
#pragma unroll
        for (int j = 0; j < 8; j++)
#pragma unroll
            for (int r = 0; r < 4; r++) acc[i][j][r] = 0.f;

    // stage tile i into buffer i&1
    auto stage = [&](int i) {
        const int b = i & 1;
        const float* xp = x + (size_t)row_base * EMB + i * 32;
        // X tile: 128 rows x 32 cols = 1024 float4
#pragma unroll
        for (int it = 0; it < 4; it++) {
            int idx = tid + it * 256;
            int r = idx >> 3, cw = (idx & 7) * 4;
            cp16(xs_a + (uint32_t)(b * XBUF + r * XSTR + cw) * 4u,
                 xp + (size_t)r * EMB + cw);
        }
        const float* wp = W + (size_t)(i * 32) * HD;
        // W tile: 32 rows x 128 cols = 1024 float4
#pragma unroll
        for (int it = 0; it < 4; it++) {
            int idx = tid + it * 256;
            int r = idx >> 5, cw = (idx & 31) * 4;
            cp16(ws_a + (uint32_t)(b * WBUF + r * WSTR + cw) * 4u,
                 wp + (size_t)r * HD + cw);
        }
    };

    stage(0);
    CP_COMMIT();

    for (int i = 0; i < 32; i++) {
        CP_WAIT0();
        __syncthreads();
        if (i + 1 < 32) stage(i + 1);
        CP_COMMIT();

        const uint32_t* Xb = Xs + (i & 1) * XBUF;
        const uint32_t* Wb = Ws + (i & 1) * WBUF;

#pragma unroll
        for (int ks = 0; ks < 4; ks++) {
            const int kk = ks * 8;
            uint32_t a[2][4];
#pragma unroll
            for (int ii = 0; ii < 2; ii++) {
                int ab = (m0 + ii * 16 + g) * XSTR + kk + t;
                a[ii][0] = f2tf(__uint_as_float(Xb[ab]));
                a[ii][1] = f2tf(__uint_as_float(Xb[ab + 8 * XSTR]));
                a[ii][2] = f2tf(__uint_as_float(Xb[ab + 4]));
                a[ii][3] = f2tf(__uint_as_float(Xb[ab + 8 * XSTR + 4]));
            }
#pragma unroll
            for (int j = 0; j < 8; j++) {
                int bb = (kk + t) * WSTR + n0 + j * 8 + g;
                uint32_t b[2] = { f2tf(__uint_as_float(Wb[bb])),
                                  f2tf(__uint_as_float(Wb[bb + 4 * WSTR])) };
                mma8(acc[0][j], a[0], b);
                mma8(acc[1][j], a[1], b);
            }
        }
    }

    // epilogue: convert to tf32 bits (Q pre-scaled)
    const float qs = (which == 0) ? rsqrtf((float)HD) : 1.f;
#pragma unroll
    for (int i = 0; i < 2; i++)
#pragma unroll
        for (int j = 0; j < 8; j++) {
            int row = row_base + m0 + i * 16 + g;
            int col = n0 + j * 8 + 2 * t;
            *(float2*)&out[(size_t)row * HD + col] = make_float2(
                __uint_as_float(f2tf(acc[i][j][0] * qs)),
                __uint_as_float(f2tf(acc[i][j][1] * qs)));
            *(float2*)&out[(size_t)(row + 8) * HD + col] = make_float2(
                __uint_as_float(f2tf(acc[i][j][2] * qs)),
                __uint_as_float(f2tf(acc[i][j][3] * qs)));
        }
}

// ---------------------------------------------------------------------------
// Kernel 2: causal flash attention, tf32 MMA.
// cp.async double-buffered K/V, one-sync local-max softmax.
// ---------------------------------------------------------------------------
#define QKSTR 132   // % 32 == 4 (Q, K)
#define VSTR  136   // % 32 == 8 (V)
#define PSTR  68    // % 32 == 4 (P)
#define KBUF  (64 * QKSTR)
#define VBUF  (64 * VSTR)

#define ATTN_SMEM_U32 (64 * QKSTR + 2 * KBUF + 2 * VBUF + 64 * PSTR + 4 * 64)
#define ATTN_SMEM_BYTES (ATTN_SMEM_U32 * 4)

// Full 64x128 tiles: 2048 float4 each -> 8 iterations of 256 threads.
__device__ __forceinline__ void stage_kv(uint32_t k_a, uint32_t v_a,
                                         const float* kp, const float* vp,
                                         int tid, int b)
{
#pragma unroll
    for (int it = 0; it < 8; it++) {
        int idx = tid + it * 256;
        int r = idx >> 5;            // 0..63
        int cw = (idx & 31) * 4;     // 0..124
        cp16(k_a + (uint32_t)(b * KBUF + r * QKSTR + cw) * 4u, kp + (size_t)r * HD + cw);
        cp16(v_a + (uint32_t)(b * VBUF + r * VSTR + cw) * 4u, vp + (size_t)r * HD + cw);
    }
}

__global__ __launch_bounds__(256) void attn_kernel(float* __restrict__ out)
{
    const int batch = blockIdx.y;
    const int qt = (int)(gridDim.x - 1) - (int)blockIdx.x;   // heavy tiles first
    const int q_base = qt * 64;
    const size_t boff = (size_t)batch * SEQ * HD;

    extern __shared__ uint32_t sm[];
    uint32_t* Qs = sm;                      // 64 x 132
    uint32_t* Ks = Qs + 64 * QKSTR;         // [2][64 x 132]
    uint32_t* Vs = Ks + 2 * KBUF;           // [2][64 x 136]
    uint32_t* Ps = Vs + 2 * VBUF;           // 64 x 68
    float* mloc = (float*)(Ps + 64 * PSTR); // [2][64]
    float* sloc = mloc + 128;               // [2][64]

    const uint32_t q_a = smem_u32(Qs);
    const uint32_t k_a = smem_u32(Ks);
    const uint32_t v_a = smem_u32(Vs);

    const int tid  = threadIdx.x;
    const int warp = tid >> 5;
    const int lane = tid & 31;
    const int g = lane >> 2;
    const int t = lane & 3;
    const int mt = warp & 3;
    const int nh = warp >> 2;
    const int m0 = mt * 16;
    const int nb = nh * 32;     // key cols for S
    const int hb = nh * 64;     // hd cols for O
    const int r0l = m0 + g;
    const int r1l = m0 + g + 8;

    // prologue: stage Q (full 64x128 = 2048 float4) + KV(0)
#pragma unroll
    for (int it = 0; it < 8; it++) {
        int idx = tid + it * 256;
        int r = idx >> 5;
        int cw = (idx & 31) * 4;
        cp16(q_a + (uint32_t)(r * QKSTR + cw) * 4u,
             g_q + boff + (size_t)(q_base + r) * HD + cw);
    }
    stage_kv(k_a, v_a, g_k + boff, g_v + boff, tid, 0);
    CP_COMMIT();

    float o[8][4];
#pragma unroll
    for (int j = 0; j < 8; j++)
#pragma unroll
        for (int r = 0; r < 4; r++) o[j][r] = 0.f;

    float m_i0 = -1e30f, m_i1 = -1e30f;
    float l_i0 = 0.f,    l_i1 = 0.f;

    for (int kt = 0; kt <= qt; kt++) {
        CP_WAIT0();
        __syncthreads();            // buf[kt&1] visible; prior-iter reads done
        if (kt + 1 <= qt)
            stage_kv(k_a, v_a,
                     g_k + boff + (size_t)(kt + 1) * 64 * HD,
                     g_v + boff + (size_t)(kt + 1) * 64 * HD,
                     tid, (kt + 1) & 1);
        CP_COMMIT();

        const uint32_t* Kb = Ks + (kt & 1) * KBUF;
        const uint32_t* Vb = Vs + (kt & 1) * VBUF;

        // S = Q @ K^T
        float s[4][4];
#pragma unroll
        for (int j = 0; j < 4; j++)
#pragma unroll
            for (int r = 0; r < 4; r++) s[j][r] = 0.f;

#pragma unroll
        for (int ks = 0; ks < 16; ks++) {
            const int kk = ks * 8;
            uint32_t a[4];
            int ab = r0l * QKSTR + kk + t;
            a[0] = Qs[ab];
            a[1] = Qs[ab + 8 * QKSTR];
            a[2] = Qs[ab + 4];
            a[3] = Qs[ab + 8 * QKSTR + 4];
#pragma unroll
            for (int j = 0; j < 4; j++) {
                int bb = (nb + j * 8 + g) * QKSTR + kk + t;
                uint32_t b[2] = { Kb[bb], Kb[bb + 4] };
                mma8(s[j], a, b);
            }
        }

        // causal mask on diagonal tile
        if (kt == qt) {
#pragma unroll
            for (int j = 0; j < 4; j++) {
                int cn = nb + j * 8 + 2 * t;
                if (cn     > r0l) s[j][0] = -1e30f;
                if (cn + 1 > r0l) s[j][1] = -1e30f;
                if (cn     > r1l) s[j][2] = -1e30f;
                if (cn + 1 > r1l) s[j][3] = -1e30f;
            }
        }

        // local (per-half) max
        float mx0 = -1e30f, mx1 = -1e30f;
#pragma unroll
        for (int j = 0; j < 4; j++) {
            mx0 = fmaxf(mx0, fmaxf(s[j][0], s[j][1]));
            mx1 = fmaxf(mx1, fmaxf(s[j][2], s[j][3]));
        }
        mx0 = fmaxf(mx0, __shfl_xor_sync(0xffffffffu, mx0, 1));
        mx0 = fmaxf(mx0, __shfl_xor_sync(0xffffffffu, mx0, 2));
        mx1 = fmaxf(mx1, __shfl_xor_sync(0xffffffffu, mx1, 1));
        mx1 = fmaxf(mx1, __shfl_xor_sync(0xffffffffu, mx1, 2));

        // exp against local max; write P (local-scaled); local sums
        float sum0 = 0.f, sum1 = 0.f;
#pragma unroll
        for (int j = 0; j < 4; j++) {
            float p00 = __expf(s[j][0] - mx0);
            float p01 = __expf(s[j][1] - mx0);
            float p10 = __expf(s[j][2] - mx1);
            float p11 = __expf(s[j][3] - mx1);
            sum0 += p00 + p01;
            sum1 += p10 + p11;
            int cn = nb + j * 8 + 2 * t;
            *(uint2*)&Ps[r0l * PSTR + cn] = make_uint2(f2tf(p00), f2tf(p01));
            *(uint2*)&Ps[r1l * PSTR + cn] = make_uint2(f2tf(p10), f2tf(p11));
        }
        sum0 += __shfl_xor_sync(0xffffffffu, sum0, 1);
        sum0 += __shfl_xor_sync(0xffffffffu, sum0, 2);
        sum1 += __shfl_xor_sync(0xffffffffu, sum1, 1);
        sum1 += __shfl_xor_sync(0xffffffffu, sum1, 2);
        if (t == 0) {
            mloc[nh * 64 + r0l] = mx0;
            mloc[nh * 64 + r1l] = mx1;
            sloc[nh * 64 + r0l] = sum0;
            sloc[nh * 64 + r1l] = sum1;
        }
        __syncthreads();            // the single softmax barrier

        const float mA0 = mloc[r0l], mB0 = mloc[64 + r0l];
        const float mA1 = mloc[r1l], mB1 = mloc[64 + r1l];
        const float m_new0 = fmaxf(m_i0, fmaxf(mA0, mB0));
        const float m_new1 = fmaxf(m_i1, fmaxf(mA1, mB1));
        const float corr0 = __expf(m_i0 - m_new0);
        const float corr1 = __expf(m_i1 - m_new1);
        const float fA0 = __expf(mA0 - m_new0), fB0 = __expf(mB0 - m_new0);
        const float fA1 = __expf(mA1 - m_new1), fB1 = __expf(mB1 - m_new1);
        l_i0 = l_i0 * corr0 + fA0 * sloc[r0l] + fB0 * sloc[64 + r0l];
        l_i1 = l_i1 * corr1 + fA1 * sloc[r1l] + fB1 * sloc[64 + r1l];
        m_i0 = m_new0;
        m_i1 = m_new1;

        // rescale O, then O += (f * P) @ V  (f folded into A fragments)
#pragma unroll
        for (int j = 0; j < 8; j++) {
            o[j][0] *= corr0; o[j][1] *= corr0;
            o[j][2] *= corr1; o[j][3] *= corr1;
        }
#pragma unroll
        for (int ks = 0; ks < 8; ks++) {
            const int kk = ks * 8;
            const float f0 = (ks < 4) ? fA0 : fB0;   // P cols 0..31 vs 32..63
            const float f1 = (ks < 4) ? fA1 : fB1;
            uint32_t a[4];
            int ab = r0l * PSTR + kk + t;
            a[0] = f2tf(__uint_as_float(Ps[ab]) * f0);
            a[1] = f2tf(__uint_as_float(Ps[ab + 8 * PSTR]) * f1);
            a[2] = f2tf(__uint_as_float(Ps[ab + 4]) * f0);
            a[3] = f2tf(__uint_as_float(Ps[ab + 8 * PSTR + 4]) * f1);
#pragma unroll
            for (int j = 0; j < 8; j++) {
                int bb = (kk + t) * VSTR + hb + j * 8 + g;
                uint32_t b[2] = { Vb[bb], Vb[bb + 4 * VSTR] };
                mma8(o[j], a, b);
            }
        }
    }

    // normalize and write
    const float inv0 = 1.f / l_i0;
    const float inv1 = 1.f / l_i1;
#pragma unroll
    for (int j = 0; j < 8; j++) {
        int col = hb + j * 8 + 2 * t;
        int row = q_base + r0l;
        *(float2*)&out[boff + (size_t)row * HD + col] =
            make_float2(o[j][0] * inv0, o[j][1] * inv0);
        *(float2*)&out[boff + (size_t)(row + 8) * HD + col] =
            make_float2(o[j][2] * inv1, o[j][3] * inv1);
    }
}

// ---------------------------------------------------------------------------
extern "C" void kernel_launch(void* const* d_in, const int* in_sizes, int n_in,
                              void* d_out, int out_size)
{
    const float* x  = (const float*)d_in[0];
    const float* Wq = (const float*)d_in[1];
    const float* Wk = (const float*)d_in[2];
    const float* Wv = (const float*)d_in[3];
    float* out = (float*)d_out;

    cudaFuncSetAttribute(qkv_kernel,
                         cudaFuncAttributeMaxDynamicSharedMemorySize,
                         QKV_SMEM_BYTES);
    cudaFuncSetAttribute(attn_kernel,
                         cudaFuncAttributeMaxDynamicSharedMemorySize,
                         ATTN_SMEM_BYTES);

    qkv_kernel<<<dim3(MTOT / 128, 3), 256, QKV_SMEM_BYTES>>>(x, Wq, Wk, Wv);
    attn_kernel<<<dim3(SEQ / 64, BATCH), 256, ATTN_SMEM_BYTES>>>(out);
}

// round 12
// speedup vs baseline: 1.2438x; 1.0104x over previous
#include <cuda_runtime.h>
#include <math.h>
#include <stdint.h>

#define BATCH 4
#define SEQ   4096
#define EMB   1024
#define HD    128
#define MTOT  (BATCH * SEQ)

// g_q, g_k: row-major [MTOT][HD], tf32 bits. g_v: TRANSPOSED [HD][MTOT], tf32 bits.
__device__ float g_q[(size_t)MTOT * HD];
__device__ float g_k[(size_t)MTOT * HD];
__device__ float g_v[(size_t)MTOT * HD];
// Transposed, tf32-converted weights: [3][HD][EMB] (Wq pre-scaled by 1/sqrt(HD))
__device__ float g_wt[(size_t)3 * HD * EMB];

// ---------------------------------------------------------------------------
// helpers
// ---------------------------------------------------------------------------
__device__ __forceinline__ uint32_t f2tf(float f) {
    uint32_t u;
    asm("cvt.rna.tf32.f32 %0, %1;" : "=r"(u) : "f"(f));
    return u;
}

__device__ __forceinline__ void mma8(float* d, const uint32_t* a, const uint32_t* b) {
    asm volatile(
        "mma.sync.aligned.m16n8k8.row.col.f32.tf32.tf32.f32 "
        "{%0,%1,%2,%3}, {%4,%5,%6,%7}, {%8,%9}, {%0,%1,%2,%3};\n"
        : "+f"(d[0]), "+f"(d[1]), "+f"(d[2]), "+f"(d[3])
        : "r"(a[0]), "r"(a[1]), "r"(a[2]), "r"(a[3]), "r"(b[0]), "r"(b[1]));
}

__device__ __forceinline__ void ldsm4(uint32_t& r0, uint32_t& r1,
                                      uint32_t& r2, uint32_t& r3, uint32_t addr) {
    asm volatile("ldmatrix.sync.aligned.m8n8.x4.shared.b16 {%0,%1,%2,%3}, [%4];"
                 : "=r"(r0), "=r"(r1), "=r"(r2), "=r"(r3) : "r"(addr));
}

__device__ __forceinline__ uint32_t smem_u32(const void* p) {
    uint32_t a;
    asm("{ .reg .u64 t; cvta.to.shared.u64 t, %1; cvt.u32.u64 %0, t; }"
        : "=r"(a) : "l"(p));
    return a;
}

__device__ __forceinline__ void cp16(uint32_t dst, const void* src) {
    asm volatile("cp.async.cg.shared.global [%0], [%1], 16;" :: "r"(dst), "l"(src));
}
#define CP_COMMIT() asm volatile("cp.async.commit_group;")
#define CP_WAIT0()  asm volatile("cp.async.wait_group 0;" ::: "memory")

// ---------------------------------------------------------------------------
// Kernel 0: transpose W [EMB][HD] -> g_wt [HD][EMB], tf32-convert, scale Wq.
// ---------------------------------------------------------------------------
__global__ __launch_bounds__(256) void prep_w(
    const float* __restrict__ Wq,
    const float* __restrict__ Wk,
    const float* __restrict__ Wv)
{
    __shared__ float tile[32][33];
    const int which = blockIdx.z;
    const float* __restrict__ W = (which == 0) ? Wq : (which == 1) ? Wk : Wv;
    float* __restrict__ out = g_wt + (size_t)which * HD * EMB;
    const int k0 = blockIdx.x * 32;
    const int n0 = blockIdx.y * 32;
    const int tx = threadIdx.x & 31;
    const int ty4 = (threadIdx.x >> 5) * 4;
#pragma unroll
    for (int i = 0; i < 4; i++)
        tile[ty4 + i][tx] = W[(size_t)(k0 + ty4 + i) * HD + n0 + tx];
    __syncthreads();
    const float s = (which == 0) ? rsqrtf((float)HD) : 1.f;
#pragma unroll
    for (int i = 0; i < 4; i++) {
        int n = ty4 + i;
        out[(size_t)(n0 + n) * EMB + k0 + tx] =
            __uint_as_float(f2tf(tile[tx][n] * s));
    }
}

// ---------------------------------------------------------------------------
// Kernel 1: QKV projection, tf32 MMA + ldmatrix, cp.async double-buffered.
// CTA tile 128(M) x 128(N), BK=32, 8 warps (32x64 warp tile).
// ---------------------------------------------------------------------------
#define XSTR 36     // % 32 == 4
#define WTSTR 36    // % 32 == 4
#define XBUF (128 * XSTR)
#define WBUF (128 * WTSTR)
#define QKV_SMEM_BYTES ((2 * XBUF + 2 * WBUF) * 4)

__global__ __launch_bounds__(256) void qkv_kernel(const float* __restrict__ x)
{
    const int which = blockIdx.y;
    const float* __restrict__ wt = g_wt + (size_t)which * HD * EMB;
    float* __restrict__ out = (which == 0) ? g_q : (which == 1) ? g_k : g_v;

    extern __shared__ uint32_t qsm[];
    uint32_t* Xs = qsm;                 // [2][128*36] raw fp32 bits (rows = m)
    uint32_t* Ws = qsm + 2 * XBUF;      // [2][128*36] tf32 bits (rows = n)
    const uint32_t xs_a = smem_u32(Xs);
    const uint32_t ws_a = smem_u32(Ws);

    const int tid  = threadIdx.x;
    const int warp = tid >> 5;
    const int lane = tid & 31;
    const int g = lane >> 2;
    const int t = lane & 3;
    const int sub = lane >> 3;
    const int rr = lane & 7;
    const int m0 = (warp & 3) * 32;
    const int n0 = (warp >> 2) * 64;
    const int row_base = blockIdx.x * 128;

    // ldmatrix per-lane base addresses (byte)
    uint32_t aX[2], bW[4];
#pragma unroll
    for (int ii = 0; ii < 2; ii++)
        aX[ii] = xs_a + (uint32_t)((m0 + ii * 16 + ((sub & 1) << 3) + rr) * XSTR
                                   + ((sub >> 1) << 2)) * 4u;
#pragma unroll
    for (int jp = 0; jp < 4; jp++)
        bW[jp] = ws_a + (uint32_t)((n0 + (jp * 2 + (sub >> 1)) * 8 + rr) * WTSTR
                                   + ((sub & 1) << 2)) * 4u;

    float acc[2][8][4];
#pragma unroll
    for (int i = 0; i < 2; i++)
#pragma unroll
        for (int j = 0; j < 8; j++)
#pragma unroll
            for (int r = 0; r < 4; r++) acc[i][j][r] = 0.f;

    auto stage = [&](int i) {
        const int b = i & 1;
        const float* xp = x + (size_t)row_base * EMB + i * 32;
        // X tile: 128 rows(m) x 32 cols(k) = 1024 float4
#pragma unroll
        for (int it = 0; it < 4; it++) {
            int idx = tid + it * 256;
            int r = idx >> 3, cw = (idx & 7) * 4;
            cp16(xs_a + (uint32_t)(b * XBUF + r * XSTR + cw) * 4u,
                 xp + (size_t)r * EMB + cw);
        }
        // Wt tile: 128 rows(n) x 32 cols(k) = 1024 float4
        const float* wp = wt + i * 32;
#pragma unroll
        for (int it = 0; it < 4; it++) {
            int idx = tid + it * 256;
            int r = idx >> 3, cw = (idx & 7) * 4;
            cp16(ws_a + (uint32_t)(b * WBUF + r * WTSTR + cw) * 4u,
                 wp + (size_t)r * EMB + cw);
        }
    };

    stage(0);
    CP_COMMIT();

    for (int i = 0; i < 32; i++) {
        CP_WAIT0();
        __syncthreads();
        if (i + 1 < 32) stage(i + 1);
        CP_COMMIT();

        const uint32_t xoff = (uint32_t)((i & 1) * XBUF) * 4u;
        const uint32_t woff = (uint32_t)((i & 1) * WBUF) * 4u;

#pragma unroll
        for (int ks = 0; ks < 4; ks++) {
            const uint32_t kkb = (uint32_t)(ks * 8) * 4u;
            uint32_t a[2][4];
#pragma unroll
            for (int ii = 0; ii < 2; ii++) {
                uint32_t r0, r1, r2, r3;
                ldsm4(r0, r1, r2, r3, aX[ii] + xoff + kkb);
                a[ii][0] = f2tf(__uint_as_float(r0));
                a[ii][1] = f2tf(__uint_as_float(r1));
                a[ii][2] = f2tf(__uint_as_float(r2));
                a[ii][3] = f2tf(__uint_as_float(r3));
            }
#pragma unroll
            for (int jp = 0; jp < 4; jp++) {
                uint32_t b[4];
                ldsm4(b[0], b[1], b[2], b[3], bW[jp] + woff + kkb);
                mma8(acc[0][jp * 2],     a[0], b);
                mma8(acc[1][jp * 2],     a[1], b);
                mma8(acc[0][jp * 2 + 1], a[0], b + 2);
                mma8(acc[1][jp * 2 + 1], a[1], b + 2);
            }
        }
    }

    // epilogue: tf32-convert; V written transposed [HD][MTOT]
    if (which == 2) {
#pragma unroll
        for (int i = 0; i < 2; i++)
#pragma unroll
            for (int j = 0; j < 8; j++) {
                int row = row_base + m0 + i * 16 + g;
                int col = n0 + j * 8 + 2 * t;
                out[(size_t)col * MTOT + row] =
                    __uint_as_float(f2tf(acc[i][j][0]));
                out[(size_t)(col + 1) * MTOT + row] =
                    __uint_as_float(f2tf(acc[i][j][1]));
                out[(size_t)col * MTOT + row + 8] =
                    __uint_as_float(f2tf(acc[i][j][2]));
                out[(size_t)(col + 1) * MTOT + row + 8] =
                    __uint_as_float(f2tf(acc[i][j][3]));
            }
    } else {
#pragma unroll
        for (int i = 0; i < 2; i++)
#pragma unroll
            for (int j = 0; j < 8; j++) {
                int row = row_base + m0 + i * 16 + g;
                int col = n0 + j * 8 + 2 * t;
                *(float2*)&out[(size_t)row * HD + col] = make_float2(
                    __uint_as_float(f2tf(acc[i][j][0])),
                    __uint_as_float(f2tf(acc[i][j][1])));
                *(float2*)&out[(size_t)(row + 8) * HD + col] = make_float2(
                    __uint_as_float(f2tf(acc[i][j][2])),
                    __uint_as_float(f2tf(acc[i][j][3])));
            }
    }
}

// ---------------------------------------------------------------------------
// Kernel 2: causal flash attention, tf32 MMA + ldmatrix.
// cp.async double-buffered K/Vt, one-sync local-max softmax.
// ---------------------------------------------------------------------------
#define QKSTR 132   // % 32 == 4
#define VTSTR 68    // % 32 == 4 (Vt rows = headdim)
#define PSTR  68    // % 32 == 4
#define KBUF  (64 * QKSTR)
#define VBUF  (128 * VTSTR)

#define ATTN_SMEM_U32 (64 * QKSTR + 2 * KBUF + 2 * VBUF + 64 * PSTR + 4 * 64)
#define ATTN_SMEM_BYTES (ATTN_SMEM_U32 * 4)

// K tile 64x128 row-major (2048 float4); Vt tile 128 rows(hd) x 64 cols(key).
__device__ __forceinline__ void stage_kv(uint32_t k_a, uint32_t v_a,
                                         const float* kp, const float* vtp,
                                         int tid, int b)
{
#pragma unroll
    for (int it = 0; it < 8; it++) {
        int idx = tid + it * 256;
        int rk = idx >> 5, ck = (idx & 31) * 4;
        cp16(k_a + (uint32_t)(b * KBUF + rk * QKSTR + ck) * 4u,
             kp + (size_t)rk * HD + ck);
        int rv = idx >> 4, cv = (idx & 15) * 4;
        cp16(v_a + (uint32_t)(b * VBUF + rv * VTSTR + cv) * 4u,
             vtp + (size_t)rv * MTOT + cv);
    }
}

__global__ __launch_bounds__(256) void attn_kernel(float* __restrict__ out)
{
    const int batch = blockIdx.y;
    const int qt = (int)(gridDim.x - 1) - (int)blockIdx.x;   // heavy tiles first
    const int q_base = qt * 64;
    const size_t boff = (size_t)batch * SEQ * HD;
    const size_t soff = (size_t)batch * SEQ;     // seq offset for Vt cols

    extern __shared__ uint32_t sm[];
    uint32_t* Qs = sm;                      // 64 x 132
    uint32_t* Ks = Qs + 64 * QKSTR;         // [2][64 x 132]
    uint32_t* Vs = Ks + 2 * KBUF;           // [2][128 x 68]  (rows = hd)
    uint32_t* Ps = Vs + 2 * VBUF;           // 64 x 68
    float* mloc = (float*)(Ps + 64 * PSTR); // [2][64]
    float* sloc = mloc + 128;               // [2][64]

    const uint32_t q_a = smem_u32(Qs);
    const uint32_t k_a = smem_u32(Ks);
    const uint32_t v_a = smem_u32(Vs);
    const uint32_t p_a = smem_u32(Ps);

    const int tid  = threadIdx.x;
    const int warp = tid >> 5;
    const int lane = tid & 31;
    const int g = lane >> 2;
    const int t = lane & 3;
    const int sub = lane >> 3;
    const int rr = lane & 7;
    const int mt = warp & 3;
    const int nh = warp >> 2;
    const int m0 = mt * 16;
    const int nb = nh * 32;     // key cols for S
    const int hb = nh * 64;     // hd cols for O
    const int r0l = m0 + g;
    const int r1l = m0 + g + 8;

    // ldmatrix per-lane base addresses
    const uint32_t aQ = q_a + (uint32_t)((m0 + ((sub & 1) << 3) + rr) * QKSTR
                                         + ((sub >> 1) << 2)) * 4u;
    const uint32_t aP = p_a + (uint32_t)((m0 + ((sub & 1) << 3) + rr) * PSTR
                                         + ((sub >> 1) << 2)) * 4u;
    uint32_t bK[2], bV[4];
#pragma unroll
    for (int jp = 0; jp < 2; jp++)
        bK[jp] = k_a + (uint32_t)((nb + (jp * 2 + (sub >> 1)) * 8 + rr) * QKSTR
                                  + ((sub & 1) << 2)) * 4u;
#pragma unroll
    for (int jp = 0; jp < 4; jp++)
        bV[jp] = v_a + (uint32_t)((hb + (jp * 2 + (sub >> 1)) * 8 + rr) * VTSTR
                                  + ((sub & 1) << 2)) * 4u;

    // prologue: stage Q (64x128) + KV(0)
#pragma unroll
    for (int it = 0; it < 8; it++) {
        int idx = tid + it * 256;
        int r = idx >> 5;
        int cw = (idx & 31) * 4;
        cp16(q_a + (uint32_t)(r * QKSTR + cw) * 4u,
             g_q + boff + (size_t)(q_base + r) * HD + cw);
    }
    stage_kv(k_a, v_a, g_k + boff, g_v + soff, tid, 0);
    CP_COMMIT();

    float o[8][4];
#pragma unroll
    for (int j = 0; j < 8; j++)
#pragma unroll
        for (int r = 0; r < 4; r++) o[j][r] = 0.f;

    float m_i0 = -1e30f, m_i1 = -1e30f;
    float l_i0 = 0.f,    l_i1 = 0.f;

    for (int kt = 0; kt <= qt; kt++) {
        CP_WAIT0();
        __syncthreads();            // buf[kt&1] visible; prior-iter reads done
        if (kt + 1 <= qt)
            stage_kv(k_a, v_a,
                     g_k + boff + (size_t)(kt + 1) * 64 * HD,
                     g_v + soff + (size_t)(kt + 1) * 64,
                     tid, (kt + 1) & 1);
        CP_COMMIT();

        const uint32_t koff = (uint32_t)((kt & 1) * KBUF) * 4u;
        const uint32_t voff = (uint32_t)((kt & 1) * VBUF) * 4u;

        // S = Q @ K^T
        float s[4][4];
#pragma unroll
        for (int j = 0; j < 4; j++)
#pragma unroll
            for (int r = 0; r < 4; r++) s[j][r] = 0.f;

#pragma unroll
        for (int ks = 0; ks < 16; ks++) {
            const uint32_t kkb = (uint32_t)(ks * 8) * 4u;
            uint32_t a[4];
            ldsm4(a[0], a[1], a[2], a[3], aQ + kkb);
#pragma unroll
            for (int jp = 0; jp < 2; jp++) {
                uint32_t b[4];
                ldsm4(b[0], b[1], b[2], b[3], bK[jp] + koff + kkb);
                mma8(s[jp * 2],     a, b);
                mma8(s[jp * 2 + 1], a, b + 2);
            }
        }

        // causal mask on diagonal tile
        if (kt == qt) {
#pragma unroll
            for (int j = 0; j < 4; j++) {
                int cn = nb + j * 8 + 2 * t;
                if (cn     > r0l) s[j][0] = -1e30f;
                if (cn + 1 > r0l) s[j][1] = -1e30f;
                if (cn     > r1l) s[j][2] = -1e30f;
                if (cn + 1 > r1l) s[j][3] = -1e30f;
            }
        }

        // local (per-half) max
        float mx0 = -1e30f, mx1 = -1e30f;
#pragma unroll
        for (int j = 0; j < 4; j++) {
            mx0 = fmaxf(mx0, fmaxf(s[j][0], s[j][1]));
            mx1 = fmaxf(mx1, fmaxf(s[j][2], s[j][3]));
        }
        mx0 = fmaxf(mx0, __shfl_xor_sync(0xffffffffu, mx0, 1));
        mx0 = fmaxf(mx0, __shfl_xor_sync(0xffffffffu, mx0, 2));
        mx1 = fmaxf(mx1, __shfl_xor_sync(0xffffffffu, mx1, 1));
        mx1 = fmaxf(mx1, __shfl_xor_sync(0xffffffffu, mx1, 2));

        // exp against local max; write P (local-scaled, tf32); local sums
        float sum0 = 0.f, sum1 = 0.f;
#pragma unroll
        for (int j = 0; j < 4; j++) {
            float p00 = __expf(s[j][0] - mx0);
            float p01 = __expf(s[j][1] - mx0);
            float p10 = __expf(s[j][2] - mx1);
            float p11 = __expf(s[j][3] - mx1);
            sum0 += p00 + p01;
            sum1 += p10 + p11;
            int cn = nb + j * 8 + 2 * t;
            *(uint2*)&Ps[r0l * PSTR + cn] = make_uint2(f2tf(p00), f2tf(p01));
            *(uint2*)&Ps[r1l * PSTR + cn] = make_uint2(f2tf(p10), f2tf(p11));
        }
        sum0 += __shfl_xor_sync(0xffffffffu, sum0, 1);
        sum0 += __shfl_xor_sync(0xffffffffu, sum0, 2);
        sum1 += __shfl_xor_sync(0xffffffffu, sum1, 1);
        sum1 += __shfl_xor_sync(0xffffffffu, sum1, 2);
        if (t == 0) {
            mloc[nh * 64 + r0l] = mx0;
            mloc[nh * 64 + r1l] = mx1;
            sloc[nh * 64 + r0l] = sum0;
            sloc[nh * 64 + r1l] = sum1;
        }
        __syncthreads();            // the single softmax barrier

        const float mA0 = mloc[r0l], mB0 = mloc[64 + r0l];
        const float mA1 = mloc[r1l], mB1 = mloc[64 + r1l];
        const float m_new0 = fmaxf(m_i0, fmaxf(mA0, mB0));
        const float m_new1 = fmaxf(m_i1, fmaxf(mA1, mB1));
        const float corr0 = __expf(m_i0 - m_new0);
        const float corr1 = __expf(m_i1 - m_new1);
        const float fA0 = __expf(mA0 - m_new0), fB0 = __expf(mB0 - m_new0);
        const float fA1 = __expf(mA1 - m_new1), fB1 = __expf(mB1 - m_new1);
        l_i0 = l_i0 * corr0 + fA0 * sloc[r0l] + fB0 * sloc[64 + r0l];
        l_i1 = l_i1 * corr1 + fA1 * sloc[r1l] + fB1 * sloc[64 + r1l];
        m_i0 = m_new0;
        m_i1 = m_new1;

        // rescale O, then O += (f * P) @ Vt
#pragma unroll
        for (int j = 0; j < 8; j++) {
            o[j][0] *= corr0; o[j][1] *= corr0;
            o[j][2] *= corr1; o[j][3] *= corr1;
        }
#pragma unroll
        for (int ks = 0; ks < 8; ks++) {
            const uint32_t kkb = (uint32_t)(ks * 8) * 4u;
            const float f0 = (ks < 4) ? fA0 : fB0;   // P cols 0..31 vs 32..63
            const float f1 = (ks < 4) ? fA1 : fB1;
            uint32_t p0, p1, p2, p3;
            ldsm4(p0, p1, p2, p3, aP + kkb);
            uint32_t a[4];
            a[0] = f2tf(__uint_as_float(p0) * f0);
            a[1] = f2tf(__uint_as_float(p1) * f1);
            a[2] = f2tf(__uint_as_float(p2) * f0);
            a[3] = f2tf(__uint_as_float(p3) * f1);
#pragma unroll
            for (int jp = 0; jp < 4; jp++) {
                uint32_t b[4];
                ldsm4(b[0], b[1], b[2], b[3], bV[jp] + voff + kkb);
                mma8(o[jp * 2],     a, b);
                mma8(o[jp * 2 + 1], a, b + 2);
            }
        }
    }

    // normalize and write
    const float inv0 = 1.f / l_i0;
    const float inv1 = 1.f / l_i1;
#pragma unroll
    for (int j = 0; j < 8; j++) {
        int col = hb + j * 8 + 2 * t;
        int row = q_base + r0l;
        *(float2*)&out[boff + (size_t)row * HD + col] =
            make_float2(o[j][0] * inv0, o[j][1] * inv0);
        *(float2*)&out[boff + (size_t)(row + 8) * HD + col] =
            make_float2(o[j][2] * inv1, o[j][3] * inv1);
    }
}

// ---------------------------------------------------------------------------
extern "C" void kernel_launch(void* const* d_in, const int* in_sizes, int n_in,
                              void* d_out, int out_size)
{
    const float* x  = (const float*)d_in[0];
    const float* Wq = (const float*)d_in[1];
    const float* Wk = (const float*)d_in[2];
    const float* Wv = (const float*)d_in[3];
    float* out = (float*)d_out;

    cudaFuncSetAttribute(qkv_kernel,
                         cudaFuncAttributeMaxDynamicSharedMemorySize,
                         QKV_SMEM_BYTES);
    cudaFuncSetAttribute(attn_kernel,
                         cudaFuncAttributeMaxDynamicSharedMemorySize,
                         ATTN_SMEM_BYTES);

    prep_w<<<dim3(EMB / 32, HD / 32, 3), 256>>>(Wq, Wk, Wv);
    qkv_kernel<<<dim3(MTOT / 128, 3), 256, QKV_SMEM_BYTES>>>(x);
    attn_kernel<<<dim3(SEQ / 64, BATCH), 256, ATTN_SMEM_BYTES>>>(out);
}

// round 13
// speedup vs baseline: 1.4481x; 1.1642x over previous
#include <cuda_runtime.h>
#include <math.h>
#include <stdint.h>

#define BATCH 4
#define SEQ   4096
#define EMB   1024
#define HD    128
#define MTOT  (BATCH * SEQ)

// g_q, g_k: row-major [MTOT][HD], tf32 bits (q pre-scaled). g_v: TRANSPOSED [HD][MTOT].
__device__ float g_q[(size_t)MTOT * HD];
__device__ float g_k[(size_t)MTOT * HD];
__device__ float g_v[(size_t)MTOT * HD];
// Transposed, tf32-converted weights: [3][HD][EMB] (Wq pre-scaled by 1/sqrt(HD))
__device__ float g_wt[(size_t)3 * HD * EMB];

// ---------------------------------------------------------------------------
// helpers
// ---------------------------------------------------------------------------
__device__ __forceinline__ uint32_t f2tf(float f) {
    uint32_t u;
    asm("cvt.rna.tf32.f32 %0, %1;" : "=r"(u) : "f"(f));
    return u;
}

__device__ __forceinline__ void mma8(float* d, const uint32_t* a, const uint32_t* b) {
    asm volatile(
        "mma.sync.aligned.m16n8k8.row.col.f32.tf32.tf32.f32 "
        "{%0,%1,%2,%3}, {%4,%5,%6,%7}, {%8,%9}, {%0,%1,%2,%3};\n"
        : "+f"(d[0]), "+f"(d[1]), "+f"(d[2]), "+f"(d[3])
        : "r"(a[0]), "r"(a[1]), "r"(a[2]), "r"(a[3]), "r"(b[0]), "r"(b[1]));
}

__device__ __forceinline__ void ldsm4(uint32_t& r0, uint32_t& r1,
                                      uint32_t& r2, uint32_t& r3, uint32_t addr) {
    asm volatile("ldmatrix.sync.aligned.m8n8.x4.shared.b16 {%0,%1,%2,%3}, [%4];"
                 : "=r"(r0), "=r"(r1), "=r"(r2), "=r"(r3) : "r"(addr));
}

__device__ __forceinline__ uint32_t smem_u32(const void* p) {
    uint32_t a;
    asm("{ .reg .u64 t; cvta.to.shared.u64 t, %1; cvt.u32.u64 %0, t; }"
        : "=r"(a) : "l"(p));
    return a;
}

__device__ __forceinline__ void cp16(uint32_t dst, const void* src) {
    asm volatile("cp.async.cg.shared.global [%0], [%1], 16;" :: "r"(dst), "l"(src));
}
#define CP_COMMIT() asm volatile("cp.async.commit_group;")
#define CP_WAIT0()  asm volatile("cp.async.wait_group 0;" ::: "memory")

// ---------------------------------------------------------------------------
// Kernel 0: transpose W [EMB][HD] -> g_wt [HD][EMB], tf32-convert, scale Wq.
// ---------------------------------------------------------------------------
__global__ __launch_bounds__(256) void prep_w(
    const float* __restrict__ Wq,
    const float* __restrict__ Wk,
    const float* __restrict__ Wv)
{
    __shared__ float tile[32][33];
    const int which = blockIdx.z;
    const float* __restrict__ W = (which == 0) ? Wq : (which == 1) ? Wk : Wv;
    float* __restrict__ out = g_wt + (size_t)which * HD * EMB;
    const int k0 = blockIdx.x * 32;
    const int n0 = blockIdx.y * 32;
    const int tx = threadIdx.x & 31;
    const int ty4 = (threadIdx.x >> 5) * 4;
#pragma unroll
    for (int i = 0; i < 4; i++)
        tile[ty4 + i][tx] = W[(size_t)(k0 + ty4 + i) * HD + n0 + tx];
    __syncthreads();
    const float s = (which == 0) ? rsqrtf((float)HD) : 1.f;
#pragma unroll
    for (int i = 0; i < 4; i++) {
        int n = ty4 + i;
        out[(size_t)(n0 + n) * EMB + k0 + tx] =
            __uint_as_float(f2tf(tile[tx][n] * s));
    }
}

// ---------------------------------------------------------------------------
// Kernel 1: QKV projection, tf32 MMA + ldmatrix, cp.async double-buffered.
// (unchanged from the passing R5 kernel)
// ---------------------------------------------------------------------------
#define XSTR 36
#define WTSTR 36
#define XBUF (128 * XSTR)
#define WBUF (128 * WTSTR)
#define QKV_SMEM_BYTES ((2 * XBUF + 2 * WBUF) * 4)

__global__ __launch_bounds__(256) void qkv_kernel(const float* __restrict__ x)
{
    const int which = blockIdx.y;
    const float* __restrict__ wt = g_wt + (size_t)which * HD * EMB;
    float* __restrict__ out = (which == 0) ? g_q : (which == 1) ? g_k : g_v;

    extern __shared__ uint32_t qsm[];
    uint32_t* Xs = qsm;
    uint32_t* Ws = qsm + 2 * XBUF;
    const uint32_t xs_a = smem_u32(Xs);
    const uint32_t ws_a = smem_u32(Ws);

    const int tid  = threadIdx.x;
    const int warp = tid >> 5;
    const int lane = tid & 31;
    const int g = lane >> 2;
    const int t = lane & 3;
    const int sub = lane >> 3;
    const int rr = lane & 7;
    const int m0 = (warp & 3) * 32;
    const int n0 = (warp >> 2) * 64;
    const int row_base = blockIdx.x * 128;

    uint32_t aX[2], bW[4];
#pragma unroll
    for (int ii = 0; ii < 2; ii++)
        aX[ii] = xs_a + (uint32_t)((m0 + ii * 16 + ((sub & 1) << 3) + rr) * XSTR
                                   + ((sub >> 1) << 2)) * 4u;
#pragma unroll
    for (int jp = 0; jp < 4; jp++)
        bW[jp] = ws_a + (uint32_t)((n0 + (jp * 2 + (sub >> 1)) * 8 + rr) * WTSTR
                                   + ((sub & 1) << 2)) * 4u;

    float acc[2][8][4];
#pragma unroll
    for (int i = 0; i < 2; i++)
#pragma unroll
        for (int j = 0; j < 8; j++)
#pragma unroll
            for (int r = 0; r < 4; r++) acc[i][j][r] = 0.f;

    auto stage = [&](int i) {
        const int b = i & 1;
        const float* xp = x + (size_t)row_base * EMB + i * 32;
#pragma unroll
        for (int it = 0; it < 4; it++) {
            int idx = tid + it * 256;
            int r = idx >> 3, cw = (idx & 7) * 4;
            cp16(xs_a + (uint32_t)(b * XBUF + r * XSTR + cw) * 4u,
                 xp + (size_t)r * EMB + cw);
        }
        const float* wp = wt + i * 32;
#pragma unroll
        for (int it = 0; it < 4; it++) {
            int idx = tid + it * 256;
            int r = idx >> 3, cw = (idx & 7) * 4;
            cp16(ws_a + (uint32_t)(b * WBUF + r * WTSTR + cw) * 4u,
                 wp + (size_t)r * EMB + cw);
        }
    };

    stage(0);
    CP_COMMIT();

    for (int i = 0; i < 32; i++) {
        CP_WAIT0();
        __syncthreads();
        if (i + 1 < 32) stage(i + 1);
        CP_COMMIT();

        const uint32_t xoff = (uint32_t)((i & 1) * XBUF) * 4u;
        const uint32_t woff = (uint32_t)((i & 1) * WBUF) * 4u;

#pragma unroll
        for (int ks = 0; ks < 4; ks++) {
            const uint32_t kkb = (uint32_t)(ks * 8) * 4u;
            uint32_t a[2][4];
#pragma unroll
            for (int ii = 0; ii < 2; ii++) {
                uint32_t r0, r1, r2, r3;
                ldsm4(r0, r1, r2, r3, aX[ii] + xoff + kkb);
                a[ii][0] = f2tf(__uint_as_float(r0));
                a[ii][1] = f2tf(__uint_as_float(r1));
                a[ii][2] = f2tf(__uint_as_float(r2));
                a[ii][3] = f2tf(__uint_as_float(r3));
            }
#pragma unroll
            for (int jp = 0; jp < 4; jp++) {
                uint32_t b[4];
                ldsm4(b[0], b[1], b[2], b[3], bW[jp] + woff + kkb);
                mma8(acc[0][jp * 2],     a[0], b);
                mma8(acc[1][jp * 2],     a[1], b);
                mma8(acc[0][jp * 2 + 1], a[0], b + 2);
                mma8(acc[1][jp * 2 + 1], a[1], b + 2);
            }
        }
    }

    if (which == 2) {
#pragma unroll
        for (int i = 0; i < 2; i++)
#pragma unroll
            for (int j = 0; j < 8; j++) {
                int row = row_base + m0 + i * 16 + g;
                int col = n0 + j * 8 + 2 * t;
                out[(size_t)col * MTOT + row] =
                    __uint_as_float(f2tf(acc[i][j][0]));
                out[(size_t)(col + 1) * MTOT + row] =
                    __uint_as_float(f2tf(acc[i][j][1]));
                out[(size_t)col * MTOT + row + 8] =
                    __uint_as_float(f2tf(acc[i][j][2]));
                out[(size_t)(col + 1) * MTOT + row + 8] =
                    __uint_as_float(f2tf(acc[i][j][3]));
            }
    } else {
#pragma unroll
        for (int i = 0; i < 2; i++)
#pragma unroll
            for (int j = 0; j < 8; j++) {
                int row = row_base + m0 + i * 16 + g;
                int col = n0 + j * 8 + 2 * t;
                *(float2*)&out[(size_t)row * HD + col] = make_float2(
                    __uint_as_float(f2tf(acc[i][j][0])),
                    __uint_as_float(f2tf(acc[i][j][1])));
                *(float2*)&out[(size_t)(row + 8) * HD + col] = make_float2(
                    __uint_as_float(f2tf(acc[i][j][2])),
                    __uint_as_float(f2tf(acc[i][j][3])));
            }
    }
}

// ---------------------------------------------------------------------------
// Kernel 2: causal flash attention. 128 threads (4 warps), each warp owns
// 16 query rows x full 64-key width. XOR-swizzled smem, single-buffered K/V,
// warp-private softmax + P region. 112 KB smem -> 2 CTAs/SM.
// ---------------------------------------------------------------------------
#define QS_U32 (64 * 128)
#define KS_U32 (64 * 128)
#define VS_U32 (128 * 64)
#define PS_U32 (4 * 16 * 64)
#define ATTN_SMEM_BYTES ((QS_U32 + KS_U32 + VS_U32 + PS_U32) * 4)   // 114688

__global__ __launch_bounds__(128) void attn_kernel(float* __restrict__ out)
{
    // balanced bid -> work-item map: pairs (b, b+148) share an SM; sums ~55.
    const int bid = blockIdx.x;
    int w;
    if (bid < 108)      w = bid;                    // light half of pairs
    else if (bid < 148) w = 216 + (bid - 108);      // heaviest 40, solo SMs
    else                w = 215 - (bid - 148);      // heavy half of pairs
    const int qt = w >> 2;
    const int batch = w & 3;
    const int q_base = qt * 64;
    const size_t boff = (size_t)batch * SEQ * HD;
    const size_t soff = (size_t)batch * SEQ;

    extern __shared__ uint32_t sm[];
    uint32_t* Qs = sm;                  // 64 rows x 128, swizzled
    uint32_t* Ks = Qs + QS_U32;         // 64 rows x 128, swizzled
    uint32_t* Vs = Ks + KS_U32;         // 128 rows(hd) x 64(key), swizzled
    uint32_t* Ps = Vs + VS_U32;         // per-warp 16 x 64, swizzled
    const uint32_t q_a = smem_u32(Qs);
    const uint32_t k_a = smem_u32(Ks);
    const uint32_t v_a = smem_u32(Vs);
    const uint32_t p_a = smem_u32(Ps);

    const int tid  = threadIdx.x;
    const int warp = tid >> 5;
    const int lane = tid & 31;
    const int g = lane >> 2;        // accumulator row within 8
    const int t = lane & 3;         // accumulator col pair
    const int sub = lane >> 3;      // ldsm matrix id
    const int rr = lane & 7;        // ldsm row within matrix (== row&7 everywhere)
    const int khA = sub >> 1;       // A-frag k-half
    const int khB = sub & 1;        // B-frag k-half

    // ldsm row-base byte addresses (swizzle XOR applied per k-chunk in-loop)
    const int rowQ = warp * 16 + ((sub & 1) << 3) + rr;
    const uint32_t aQ_base = q_a + (uint32_t)rowQ * (128 * 4);
    uint32_t bK_base[4];
#pragma unroll
    for (int jp = 0; jp < 4; jp++) {
        int rowK = ((jp * 2 + (sub >> 1)) << 3) + rr;
        bK_base[jp] = k_a + (uint32_t)rowK * (128 * 4);
    }
    uint32_t bV_base[8];
#pragma unroll
    for (int jp = 0; jp < 8; jp++) {
        int rowV = ((jp * 2 + (sub >> 1)) << 3) + rr;
        bV_base[jp] = v_a + (uint32_t)rowV * (64 * 4);
    }
    const int rowP = ((sub & 1) << 3) + rr;
    const uint32_t aP_base = p_a + (uint32_t)(warp * 16 * 64 + rowP * 64) * 4u;

    // single-buffer K/V staging (swizzled)
    auto stage_kv = [&](int kt2) {
        const float* kp = g_k + boff + (size_t)kt2 * 64 * HD;
        const float* vp = g_v + soff + (size_t)kt2 * 64;
#pragma unroll
        for (int it = 0; it < 16; it++) {
            int idx = tid + it * 128;
            int rk = idx >> 5, ck = idx & 31;
            cp16(k_a + (uint32_t)(rk * 128 + ((ck ^ (rk & 7)) << 2)) * 4u,
                 kp + (size_t)rk * HD + ck * 4);
            int rv = idx >> 4, cv = idx & 15;
            cp16(v_a + (uint32_t)(rv * 64 + ((cv ^ (rv & 7)) << 2)) * 4u,
                 vp + (size_t)rv * MTOT + cv * 4);
        }
    };

    // prologue: Q (64x128) + KV(0)
#pragma unroll
    for (int it = 0; it < 16; it++) {
        int idx = tid + it * 128;
        int r = idx >> 5, c4 = idx & 31;
        cp16(q_a + (uint32_t)(r * 128 + ((c4 ^ (r & 7)) << 2)) * 4u,
             g_q + boff + (size_t)(q_base + r) * HD + c4 * 4);
    }
    stage_kv(0);
    CP_COMMIT();

    float o[16][4];
#pragma unroll
    for (int j = 0; j < 16; j++)
#pragma unroll
        for (int r = 0; r < 4; r++) o[j][r] = 0.f;
    float m_i0 = -1e30f, m_i1 = -1e30f;
    float l_i0 = 0.f,    l_i1 = 0.f;

    const int lrow0 = warp * 16 + g;        // CTA-local query rows
    const int lrow1 = lrow0 + 8;

    for (int kt = 0; kt <= qt; kt++) {
        CP_WAIT0();
        __syncthreads();        // tile kt visible to all warps

        // ---- S = Q @ K^T  (16 rows x 64 keys per warp) ----
        float s[8][4];
#pragma unroll
        for (int j = 0; j < 8; j++)
#pragma unroll
            for (int r = 0; r < 4; r++) s[j][r] = 0.f;

#pragma unroll
        for (int ks = 0; ks < 16; ks++) {
            uint32_t a[4];
            ldsm4(a[0], a[1], a[2], a[3],
                  aQ_base + ((uint32_t)((2 * ks + khA) ^ rr) << 4));
#pragma unroll
            for (int jp = 0; jp < 4; jp++) {
                uint32_t b[4];
                ldsm4(b[0], b[1], b[2], b[3],
                      bK_base[jp] + ((uint32_t)((2 * ks + khB) ^ rr) << 4));
                mma8(s[jp * 2],     a, b);
                mma8(s[jp * 2 + 1], a, b + 2);
            }
        }

        // ---- causal mask on diagonal tile ----
        if (kt == qt) {
#pragma unroll
            for (int j = 0; j < 8; j++) {
                int cn = j * 8 + 2 * t;
                if (cn     > lrow0) s[j][0] = -1e30f;
                if (cn + 1 > lrow0) s[j][1] = -1e30f;
                if (cn     > lrow1) s[j][2] = -1e30f;
                if (cn + 1 > lrow1) s[j][3] = -1e30f;
            }
        }

        // ---- warp-private online softmax (full 64-key row) ----
        float mx0 = -1e30f, mx1 = -1e30f;
#pragma unroll
        for (int j = 0; j < 8; j++) {
            mx0 = fmaxf(mx0, fmaxf(s[j][0], s[j][1]));
            mx1 = fmaxf(mx1, fmaxf(s[j][2], s[j][3]));
        }
        mx0 = fmaxf(mx0, __shfl_xor_sync(0xffffffffu, mx0, 1));
        mx0 = fmaxf(mx0, __shfl_xor_sync(0xffffffffu, mx0, 2));
        mx1 = fmaxf(mx1, __shfl_xor_sync(0xffffffffu, mx1, 1));
        mx1 = fmaxf(mx1, __shfl_xor_sync(0xffffffffu, mx1, 2));

        const float m_new0 = fmaxf(m_i0, mx0);
        const float m_new1 = fmaxf(m_i1, mx1);
        const float corr0 = __expf(m_i0 - m_new0);
        const float corr1 = __expf(m_i1 - m_new1);

        float sum0 = 0.f, sum1 = 0.f;
#pragma unroll
        for (int j = 0; j < 8; j++) {
            float p00 = __expf(s[j][0] - m_new0);
            float p01 = __expf(s[j][1] - m_new0);
            float p10 = __expf(s[j][2] - m_new1);
            float p11 = __expf(s[j][3] - m_new1);
            sum0 += p00 + p01;
            sum1 += p10 + p11;
            // P store: row g / g+8, cols j*8+2t, 2t+1; swizzled chunk
            int c4 = j * 2 + (t >> 1);
            int e  = 2 * (t & 1);
            uint32_t off0 = (uint32_t)(warp * 1024 + g * 64 + ((c4 ^ g) << 2) + e);
            *(uint2*)&Ps[off0]            = make_uint2(f2tf(p00), f2tf(p01));
            *(uint2*)&Ps[off0 + 8 * 64]   = make_uint2(f2tf(p10), f2tf(p11));
        }
        sum0 += __shfl_xor_sync(0xffffffffu, sum0, 1);
        sum0 += __shfl_xor_sync(0xffffffffu, sum0, 2);
        sum1 += __shfl_xor_sync(0xffffffffu, sum1, 1);
        sum1 += __shfl_xor_sync(0xffffffffu, sum1, 2);
        l_i0 = l_i0 * corr0 + sum0;
        l_i1 = l_i1 * corr1 + sum1;
        m_i0 = m_new0;
        m_i1 = m_new1;

        // rescale O
#pragma unroll
        for (int j = 0; j < 16; j++) {
            o[j][0] *= corr0; o[j][1] *= corr0;
            o[j][2] *= corr1; o[j][3] *= corr1;
        }
        __syncwarp();       // P visible within warp

        // ---- O += P @ Vt  (16 rows x 128 hd, k = 64) ----
#pragma unroll
        for (int kb = 0; kb < 8; kb++) {
            uint32_t a[4];
            ldsm4(a[0], a[1], a[2], a[3],
                  aP_base + ((uint32_t)((2 * kb + khA) ^ rr) << 4));
#pragma unroll
            for (int jp = 0; jp < 8; jp++) {
                uint32_t b[4];
                ldsm4(b[0], b[1], b[2], b[3],
                      bV_base[jp] + ((uint32_t)((2 * kb + khB) ^ rr) << 4));
                mma8(o[jp * 2],     a, b);
                mma8(o[jp * 2 + 1], a, b + 2);
            }
        }

        __syncthreads();    // all warps done reading K/V tile kt
        if (kt + 1 <= qt) stage_kv(kt + 1);
        CP_COMMIT();
    }

    // ---- normalize and write ----
    const float inv0 = 1.f / l_i0;
    const float inv1 = 1.f / l_i1;
    const int grow = q_base + lrow0;
#pragma unroll
    for (int j = 0; j < 16; j++) {
        int col = j * 8 + 2 * t;
        *(float2*)&out[boff + (size_t)grow * HD + col] =
            make_float2(o[j][0] * inv0, o[j][1] * inv0);
        *(float2*)&out[boff + (size_t)(grow + 8) * HD + col] =
            make_float2(o[j][2] * inv1, o[j][3] * inv1);
    }
}

// ---------------------------------------------------------------------------
extern "C" void kernel_launch(void* const* d_in, const int* in_sizes, int n_in,
                              void* d_out, int out_size)
{
    const float* x  = (const float*)d_in[0];
    const float* Wq = (const float*)d_in[1];
    const float* Wk = (const float*)d_in[2];
    const float* Wv = (const float*)d_in[3];
    float* out = (float*)d_out;

    cudaFuncSetAttribute(qkv_kernel,
                         cudaFuncAttributeMaxDynamicSharedMemorySize,
                         QKV_SMEM_BYTES);
    cudaFuncSetAttribute(attn_kernel,
                         cudaFuncAttributeMaxDynamicSharedMemorySize,
                         ATTN_SMEM_BYTES);

    prep_w<<<dim3(EMB / 32, HD / 32, 3), 256>>>(Wq, Wk, Wv);
    qkv_kernel<<<dim3(MTOT / 128, 3), 256, QKV_SMEM_BYTES>>>(x);
    attn_kernel<<<dim3(BATCH * SEQ / 64, 1), 128, ATTN_SMEM_BYTES>>>(out);
}